// round 2
// baseline (speedup 1.0000x reference)
#include <cuda_runtime.h>
#include <math.h>

// Problem constants
#define BB 32
#define SS 4096
#define KD 512
#define HD 512
#define NEGV (-1e9f)

// Output layout: [att_vector (32*512) | al_a (32*4096) | al_b (32*4096)]
#define OUT_ATT 0
#define OUT_AL  (BB*HD)

// Scratch (device globals; no allocations allowed)
__device__ float g_pq[2][BB][HD];
__device__ float g_scores[2][BB][SS];
__device__ float g_ctx[2][BB][KD];
__device__ float g_maskf[2][BB][SS];
__device__ int   g_mask_mode;

// ---------------------------------------------------------------------------
// Fast-but-accurate tanh (abs err ~1e-6)
__device__ __forceinline__ float tanh_fast(float x) {
    float cx = fminf(fmaxf(x, -15.0f), 15.0f);
    float e = __expf(2.0f * cx);
    return __fdividef(e - 1.0f, e + 1.0f);
}

// ---------------------------------------------------------------------------
// Mask dtype detection: scan first 32768 bytes of mask_a (safe for u8/i32/f32
// encodings of 131072 elements). Classify by which byte-lanes hold nonzeros.
__global__ void detect_kernel(const unsigned char* __restrict__ m) {
    __shared__ int c[4];
    if (threadIdx.x < 4) c[threadIdx.x] = 0;
    __syncthreads();
    int local[4] = {0, 0, 0, 0};
    for (int i = threadIdx.x; i < 32768; i += blockDim.x)
        if (m[i]) local[i & 3]++;
    #pragma unroll
    for (int j = 0; j < 4; j++) if (local[j]) atomicAdd(&c[j], local[j]);
    __syncthreads();
    if (threadIdx.x == 0) {
        int mode;
        if (c[1] > 0)      mode = 0;  // uint8/bool bytes
        else if (c[0] > 0) mode = 1;  // int32 0/1
        else               mode = 2;  // float32 0.0/1.0
        g_mask_mode = mode;
    }
}

// Convert both masks to normalized float (1.0 keep / 0.0 drop)
__global__ void mask_convert_kernel(const void* __restrict__ ma,
                                    const void* __restrict__ mb) {
    int idx = blockIdx.x * blockDim.x + threadIdx.x;    // 0 .. 2*131072-1
    int head = idx >> 17;
    int i    = idx & 131071;
    const void* p = head ? mb : ma;
    int mode = g_mask_mode;
    float keep;
    if (mode == 0)      keep = ((const unsigned char*)p)[i] ? 1.0f : 0.0f;
    else if (mode == 1) keep = ((const int*)p)[i] ? 1.0f : 0.0f;
    else                keep = (((const float*)p)[i] != 0.0f) ? 1.0f : 0.0f;
    ((float*)g_maskf)[idx] = keep;
}

// ---------------------------------------------------------------------------
// Zero the scores scratch (accumulated via atomicAdd in score_kernel)
__global__ void zero_kernel() {
    int i = blockIdx.x * blockDim.x + threadIdx.x;   // 2*32*4096 = 262144
    ((float*)g_scores)[i] = 0.0f;
}

// ---------------------------------------------------------------------------
// Phase 0: pq[head][b][h] = sum_k query[b][k] * Wq[k][h]
__global__ void pq_kernel(const float* __restrict__ query,
                          const float* __restrict__ Wq_a,
                          const float* __restrict__ Wq_b) {
    int head = blockIdx.x >> 5;
    int b    = blockIdx.x & 31;
    const float* Wq = head ? Wq_b : Wq_a;
    __shared__ float q[HD];
    int t = threadIdx.x;  // 512
    q[t] = query[b * HD + t];
    __syncthreads();
    float s = 0.0f;
    #pragma unroll 4
    for (int k = 0; k < HD; k++) s = fmaf(q[k], Wq[k * HD + t], s);
    g_pq[head][b][t] = s;
}

// ---------------------------------------------------------------------------
// Phase 1 (hot): fused GEMM + tanh epilogue.
// Block tile: 128 rows (s) x 128 cols (h), K staged in chunks of 64.
// Thread: 8x8 microtile. Grid: (nc=4, sc=32, head*32+b = 64).
#define SMEM_FLOATS (64*132 + 64*128)
__global__ __launch_bounds__(256, 2)
void score_kernel(const float* __restrict__ values_a,
                  const float* __restrict__ values_b,
                  const float* __restrict__ Wk_a,
                  const float* __restrict__ Wk_b,
                  const float* __restrict__ v_a,
                  const float* __restrict__ v_b) {
    int nc = blockIdx.x;         // 0..3  (h chunk of 128)
    int sc = blockIdx.y;         // 0..31 (s chunk of 128)
    int zb = blockIdx.z;         // 0..63
    int head = zb >> 5;
    int b    = zb & 31;
    const float* V  = head ? values_b : values_a;
    const float* Wk = head ? Wk_b : Wk_a;
    const float* vv = head ? v_b : v_a;

    extern __shared__ float sh[];
    float* As = sh;              // [64][132] transposed: As[k][r]
    float* Bs = sh + 64 * 132;   // [64][128]: Bs[k][c]

    int tid = threadIdx.x;
    int tx = tid & 15;           // col group
    int ty = tid >> 4;           // row group

    float acc[8][8];
    #pragma unroll
    for (int i = 0; i < 8; i++)
        #pragma unroll
        for (int j = 0; j < 8; j++) acc[i][j] = 0.0f;

    const float* Vbase = V + ((size_t)b * SS + (size_t)sc * 128) * KD;
    const float* Wbase = Wk + nc * 128;

    for (int kk = 0; kk < KD; kk += 64) {
        __syncthreads();
        // Stage A (values) transposed into shared
        #pragma unroll
        for (int i = 0; i < 8; i++) {
            int idx = tid + i * 256;          // 0..2047
            int r  = idx >> 4;                // 0..127
            int kq = idx & 15;                // 0..15 (float4 index within 64)
            float4 val = *(const float4*)(Vbase + (size_t)r * KD + kk + kq * 4);
            As[(kq * 4 + 0) * 132 + r] = val.x;
            As[(kq * 4 + 1) * 132 + r] = val.y;
            As[(kq * 4 + 2) * 132 + r] = val.z;
            As[(kq * 4 + 3) * 132 + r] = val.w;
        }
        // Stage B (Wk) directly
        #pragma unroll
        for (int i = 0; i < 8; i++) {
            int idx = tid + i * 256;
            int k  = idx >> 5;                // 0..63
            int cq = idx & 31;                // 0..31
            *(float4*)(Bs + k * 128 + cq * 4) =
                *(const float4*)(Wbase + (size_t)(kk + k) * HD + cq * 4);
        }
        __syncthreads();
        #pragma unroll 4
        for (int k = 0; k < 64; k++) {
            float4 a0 = *(const float4*)(As + k * 132 + ty * 8);
            float4 a1 = *(const float4*)(As + k * 132 + ty * 8 + 4);
            float4 b0 = *(const float4*)(Bs + k * 128 + tx * 8);
            float4 b1 = *(const float4*)(Bs + k * 128 + tx * 8 + 4);
            float av[8] = {a0.x, a0.y, a0.z, a0.w, a1.x, a1.y, a1.z, a1.w};
            float bw[8] = {b0.x, b0.y, b0.z, b0.w, b1.x, b1.y, b1.z, b1.w};
            #pragma unroll
            for (int i = 0; i < 8; i++)
                #pragma unroll
                for (int j = 0; j < 8; j++)
                    acc[i][j] = fmaf(av[i], bw[j], acc[i][j]);
        }
    }

    // Epilogue: partial score per row = sum_c v[c] * tanh(pq[c] + acc)
    int h0 = nc * 128 + tx * 8;
    float pqv[8], vw[8];
    #pragma unroll
    for (int j = 0; j < 8; j++) {
        pqv[j] = g_pq[head][b][h0 + j];
        vw[j]  = vv[h0 + j];
    }
    float rowsum[8];
    #pragma unroll
    for (int i = 0; i < 8; i++) {
        float p = 0.0f;
        #pragma unroll
        for (int j = 0; j < 8; j++) {
            float t = tanh_fast(acc[i][j] + pqv[j]);
            p = fmaf(vw[j], t, p);
        }
        rowsum[i] = p;
    }
    // Reduce across the 16 tx lanes (within each 16-lane half-warp)
    #pragma unroll
    for (int off = 8; off > 0; off >>= 1)
        #pragma unroll
        for (int i = 0; i < 8; i++)
            rowsum[i] += __shfl_xor_sync(0xffffffffu, rowsum[i], off);
    if (tx == 0) {
        int srow = sc * 128 + ty * 8;
        #pragma unroll
        for (int i = 0; i < 8; i++)
            atomicAdd(&g_scores[head][b][srow + i], rowsum[i]);
    }
}

// ---------------------------------------------------------------------------
// Phase 2: mask + sparsemax (binary search on tau) + context + write alphas.
// One block per (head, b). 512 threads.
__global__ void sparsemax_kernel(const float* __restrict__ values_a,
                                 const float* __restrict__ values_b,
                                 float* __restrict__ out) {
    int head = blockIdx.x >> 5;
    int b    = blockIdx.x & 31;
    const float* V = head ? values_b : values_a;

    __shared__ float z[SS];      // 16KB
    __shared__ float wred[16];
    __shared__ float bcast;

    int tid  = threadIdx.x;
    int lane = tid & 31;
    int wid  = tid >> 5;

    // Load + mask + local max
    float lmax = -3.0e38f;
    for (int i = tid; i < SS; i += 512) {
        float sc = g_scores[head][b][i];
        float zz = (g_maskf[head][b][i] != 0.0f) ? sc : NEGV;
        z[i] = zz;
        lmax = fmaxf(lmax, zz);
    }
    #pragma unroll
    for (int off = 16; off > 0; off >>= 1)
        lmax = fmaxf(lmax, __shfl_xor_sync(0xffffffffu, lmax, off));
    if (lane == 0) wred[wid] = lmax;
    __syncthreads();
    if (tid == 0) {
        float m = wred[0];
        for (int w = 1; w < 16; w++) m = fmaxf(m, wred[w]);
        bcast = m;
    }
    __syncthreads();
    float zmax = bcast;

    // Binary search: tau in [zmax-1, zmax], f(tau)=sum max(z-tau,0) decreasing, f(tau*)=1
    float lo = zmax - 1.0f, hi = zmax;
    for (int it = 0; it < 40; it++) {
        float mid = 0.5f * (lo + hi);
        float s = 0.0f;
        for (int i = tid; i < SS; i += 512) s += fmaxf(z[i] - mid, 0.0f);
        #pragma unroll
        for (int off = 16; off > 0; off >>= 1)
            s += __shfl_xor_sync(0xffffffffu, s, off);
        if (lane == 0) wred[wid] = s;
        __syncthreads();
        if (tid == 0) {
            float tot = 0.0f;
            for (int w = 0; w < 16; w++) tot += wred[w];
            bcast = tot;
        }
        __syncthreads();
        float tot = bcast;
        if (tot >= 1.0f) lo = mid; else hi = mid;
        __syncthreads();
    }
    float tau = 0.5f * (lo + hi);

    // Alphas -> output and back into shared for the context pass
    float* alout = out + OUT_AL + (size_t)head * BB * SS + (size_t)b * SS;
    for (int i = tid; i < SS; i += 512) {
        float a = fmaxf(z[i] - tau, 0.0f);
        alout[i] = a;
        z[i] = a;
    }
    __syncthreads();

    // context[k] = sum_s alpha_s * values[b][s][k]   (sparse support)
    const float* Vb = V + (size_t)b * SS * KD;
    float ctx = 0.0f;
    for (int s = 0; s < SS; s++) {
        float a = z[s];
        if (a > 0.0f) ctx = fmaf(a, Vb[(size_t)s * KD + tid], ctx);
    }
    g_ctx[head][b][tid] = ctx;
}

// ---------------------------------------------------------------------------
// Phase 3: gate softmax + candidates + blend. One block per b, 512 threads.
__global__ void merge_kernel(const float* __restrict__ query,
                             const float* __restrict__ Wg,
                             const float* __restrict__ bg,
                             const float* __restrict__ Wu_a,
                             const float* __restrict__ bu_a,
                             const float* __restrict__ Wu_b,
                             const float* __restrict__ bu_b,
                             float* __restrict__ out) {
    int b = blockIdx.x;
    int t = threadIdx.x;   // 512
    int lane = t & 31, wid = t >> 5;
    __shared__ float qv[HD], ca[KD], cb[KD];
    __shared__ float red0[16], red1[16];
    __shared__ float w01[2];

    qv[t] = query[b * HD + t];
    ca[t] = g_ctx[0][b][t];
    cb[t] = g_ctx[1][b][t];
    __syncthreads();

    // Gate logits: gate_in = [q | ctx_a | ctx_b] (1536) @ Wg (1536x2) + bg
    float p0 = 0.0f, p1 = 0.0f;
    {
        float x = qv[t];
        p0 = fmaf(x, Wg[t * 2 + 0], p0);  p1 = fmaf(x, Wg[t * 2 + 1], p1);
        x = ca[t];
        p0 = fmaf(x, Wg[(512 + t) * 2 + 0], p0);  p1 = fmaf(x, Wg[(512 + t) * 2 + 1], p1);
        x = cb[t];
        p0 = fmaf(x, Wg[(1024 + t) * 2 + 0], p0); p1 = fmaf(x, Wg[(1024 + t) * 2 + 1], p1);
    }
    #pragma unroll
    for (int off = 16; off > 0; off >>= 1) {
        p0 += __shfl_xor_sync(0xffffffffu, p0, off);
        p1 += __shfl_xor_sync(0xffffffffu, p1, off);
    }
    if (lane == 0) { red0[wid] = p0; red1[wid] = p1; }
    __syncthreads();
    if (t == 0) {
        float g0 = bg[0], g1 = bg[1];
        for (int w = 0; w < 16; w++) { g0 += red0[w]; g1 += red1[w]; }
        float m = fmaxf(g0, g1);
        float e0 = expf(g0 - m), e1 = expf(g1 - m);
        float inv = 1.0f / (e0 + e1);
        w01[0] = e0 * inv;
        w01[1] = e1 * inv;
    }
    __syncthreads();
    float w0 = w01[0], w1 = w01[1];

    // Candidates: cand = tanh([q | ctx] @ Wu + bu)
    float sa = bu_a[t], sb = bu_b[t];
    for (int i = 0; i < 512; i++) {
        float q = qv[i];
        sa = fmaf(q, Wu_a[i * HD + t], sa);
        sb = fmaf(q, Wu_b[i * HD + t], sb);
    }
    for (int i = 0; i < 512; i++) {
        sa = fmaf(ca[i], Wu_a[(512 + i) * HD + t], sa);
        sb = fmaf(cb[i], Wu_b[(512 + i) * HD + t], sb);
    }
    out[OUT_ATT + b * HD + t] = w0 * tanhf(sa) + w1 * tanhf(sb);
}

// ---------------------------------------------------------------------------
extern "C" void kernel_launch(void* const* d_in, const int* in_sizes, int n_in,
                              void* d_out, int out_size) {
    const float* query    = (const float*)d_in[0];
    const float* values_a = (const float*)d_in[1];
    const float* values_b = (const float*)d_in[2];
    const void*  mask_a   = d_in[3];
    const void*  mask_b   = d_in[4];
    const float* Wk_a = (const float*)d_in[5];
    const float* Wq_a = (const float*)d_in[6];
    const float* v_a  = (const float*)d_in[7];
    const float* Wk_b = (const float*)d_in[8];
    const float* Wq_b = (const float*)d_in[9];
    const float* v_b  = (const float*)d_in[10];
    const float* Wg   = (const float*)d_in[11];
    const float* bg   = (const float*)d_in[12];
    const float* Wu_a = (const float*)d_in[13];
    const float* bu_a = (const float*)d_in[14];
    const float* Wu_b = (const float*)d_in[15];
    const float* bu_b = (const float*)d_in[16];
    float* out = (float*)d_out;

    const int smem_bytes = SMEM_FLOATS * (int)sizeof(float);  // 66560
    cudaFuncSetAttribute(score_kernel,
                         cudaFuncAttributeMaxDynamicSharedMemorySize, smem_bytes);

    detect_kernel<<<1, 256>>>((const unsigned char*)mask_a);
    mask_convert_kernel<<<512, 512>>>(mask_a, mask_b);
    zero_kernel<<<512, 512>>>();
    pq_kernel<<<64, 512>>>(query, Wq_a, Wq_b);
    dim3 g1(4, 32, 64);
    score_kernel<<<g1, 256, smem_bytes>>>(values_a, values_b, Wk_a, Wk_b, v_a, v_b);
    sparsemax_kernel<<<64, 512>>>(values_a, values_b, out);
    merge_kernel<<<32, 512>>>(query, Wg, bg, Wu_a, bu_a, Wu_b, bu_b, out);
}

// round 4
// speedup vs baseline: 2.5107x; 2.5107x over previous
#include <cuda_runtime.h>
#include <cuda_bf16.h>
#include <math.h>
#include <stdint.h>

// Problem constants
#define BB 32
#define SS 4096
#define KD 512
#define HD 512
#define NEGV (-1e9f)

// Output layout: [att_vector (32*512) | al_a (32*4096) | al_b (32*4096)]
#define OUT_ATT 0
#define OUT_AL  (BB*HD)

// Scratch (device globals; no allocations allowed)
__device__ float g_pq[2][BB][HD];
__device__ float g_scp[4][2][BB][SS];   // [nh][head][b][s] partial scores
__device__ float g_ctx[2][BB][KD];
__device__ float g_maskf[2][BB][SS];
__device__ int   g_mask_mode;
// Pre-split, transposed Wk images: g_Bt[head][n][k] = split(Wk[k][n])
__device__ __nv_bfloat16 g_Bt_hi[2][HD][KD];
__device__ __nv_bfloat16 g_Bt_lo[2][HD][KD];

// ---------------------------------------------------------------------------
__device__ __forceinline__ float tanh_fast(float x) {
    float cx = fminf(fmaxf(x, -15.0f), 15.0f);
    float e = __expf(2.0f * cx);
    return __fdividef(e - 1.0f, e + 1.0f);
}

__device__ __forceinline__ uint32_t smem_u32(const void* p) {
    uint32_t a;
    asm("{ .reg .u64 t; cvta.to.shared.u64 t, %1; cvt.u32.u64 %0, t; }"
        : "=r"(a) : "l"(p));
    return a;
}

// pack two floats -> bf16x2 (x0 low half, x1 high half)
__device__ __forceinline__ uint32_t pack_bf2(float x0, float x1) {
    uint32_t d;
    asm("cvt.rn.satfinite.bf16x2.f32 %0, %1, %2;" : "=r"(d) : "f"(x1), "f"(x0));
    return d;
}

__device__ __forceinline__ void ldsm4(uint32_t& r0, uint32_t& r1,
                                      uint32_t& r2, uint32_t& r3, uint32_t a) {
    asm volatile("ldmatrix.sync.aligned.m8n8.x4.shared.b16 {%0,%1,%2,%3}, [%4];"
                 : "=r"(r0), "=r"(r1), "=r"(r2), "=r"(r3) : "r"(a));
}

__device__ __forceinline__ void mma_bf16(float* c, const uint32_t* a,
                                         const uint32_t* b) {
    asm volatile(
        "mma.sync.aligned.m16n8k16.row.col.f32.bf16.bf16.f32 "
        "{%0,%1,%2,%3}, {%4,%5,%6,%7}, {%8,%9}, {%0,%1,%2,%3};"
        : "+f"(c[0]), "+f"(c[1]), "+f"(c[2]), "+f"(c[3])
        : "r"(a[0]), "r"(a[1]), "r"(a[2]), "r"(a[3]), "r"(b[0]), "r"(b[1]));
}

// ---------------------------------------------------------------------------
// Mask dtype detection (int32 on this dataset, keep generic)
__global__ void detect_kernel(const unsigned char* __restrict__ m) {
    __shared__ int c[4];
    if (threadIdx.x < 4) c[threadIdx.x] = 0;
    __syncthreads();
    int local[4] = {0, 0, 0, 0};
    for (int i = threadIdx.x; i < 32768; i += blockDim.x)
        if (m[i]) local[i & 3]++;
    #pragma unroll
    for (int j = 0; j < 4; j++) if (local[j]) atomicAdd(&c[j], local[j]);
    __syncthreads();
    if (threadIdx.x == 0) {
        int mode;
        if (c[1] > 0)      mode = 0;
        else if (c[0] > 0) mode = 1;
        else               mode = 2;
        g_mask_mode = mode;
    }
}

__global__ void mask_convert_kernel(const void* __restrict__ ma,
                                    const void* __restrict__ mb) {
    int idx = blockIdx.x * blockDim.x + threadIdx.x;
    int head = idx >> 17;
    int i    = idx & 131071;
    const void* p = head ? mb : ma;
    int mode = g_mask_mode;
    float keep;
    if (mode == 0)      keep = ((const unsigned char*)p)[i] ? 1.0f : 0.0f;
    else if (mode == 1) keep = ((const int*)p)[i] ? 1.0f : 0.0f;
    else                keep = (((const float*)p)[i] != 0.0f) ? 1.0f : 0.0f;
    ((float*)g_maskf)[idx] = keep;
}

// ---------------------------------------------------------------------------
// Transpose + split Wk into g_Bt_hi/lo[head][n][k]. Tiled via smem.
// Grid: (16 kt, 16 nt, 2 head), block (32, 8).
__global__ void prep_wk_kernel(const float* __restrict__ Wk_a,
                               const float* __restrict__ Wk_b) {
    __shared__ float tile[32][33];
    int head = blockIdx.z;
    const float* Wk = head ? Wk_b : Wk_a;
    int kt = blockIdx.x * 32, nt = blockIdx.y * 32;
    int tx = threadIdx.x, ty = threadIdx.y;
    #pragma unroll
    for (int i = 0; i < 4; i++)
        tile[ty + i * 8][tx] = Wk[(kt + ty + i * 8) * HD + nt + tx];
    __syncthreads();
    #pragma unroll
    for (int i = 0; i < 4; i++) {
        int n = nt + ty + i * 8;
        int k = kt + tx;
        float x = tile[tx][ty + i * 8];
        __nv_bfloat16 h = __float2bfloat16(x);
        float hf = __bfloat162float(h);
        g_Bt_hi[head][n][k] = h;
        g_Bt_lo[head][n][k] = __float2bfloat16(x - hf);
    }
}

// ---------------------------------------------------------------------------
// pq[head][b][h] = sum_k query[b][k] * Wq[k][h]
__global__ void pq_kernel(const float* __restrict__ query,
                          const float* __restrict__ Wq_a,
                          const float* __restrict__ Wq_b) {
    int head = blockIdx.x >> 5;
    int b    = blockIdx.x & 31;
    const float* Wq = head ? Wq_b : Wq_a;
    __shared__ float q[HD];
    int t = threadIdx.x;
    q[t] = query[b * HD + t];
    __syncthreads();
    float s0 = 0.f, s1 = 0.f, s2 = 0.f, s3 = 0.f;
    #pragma unroll 4
    for (int k = 0; k < HD; k += 4) {
        s0 = fmaf(q[k + 0], Wq[(k + 0) * HD + t], s0);
        s1 = fmaf(q[k + 1], Wq[(k + 1) * HD + t], s1);
        s2 = fmaf(q[k + 2], Wq[(k + 2) * HD + t], s2);
        s3 = fmaf(q[k + 3], Wq[(k + 3) * HD + t], s3);
    }
    g_pq[head][b][t] = (s0 + s1) + (s2 + s3);
}

// ---------------------------------------------------------------------------
// Hot kernel: bf16 split mma.sync GEMM + tanh/v epilogue.
// Grid (sc=32, nh=4, zb=64), block 256 (8 warps: 2m x 4n). Tile 128x128, k64.
// smem rows: 72 bf16 (144B) stride -> conflict-free ldmatrix.
#define SMA_HI 0
#define SMA_LO 18432
#define SMB_HI 36864
#define SMB_LO 55296
#define SM_PS  73728
#define SM_VS  74240
#define SM_RED 74752
#define SM_TOTAL 76800

__global__ __launch_bounds__(256, 2)
void score_mma_kernel(const float* __restrict__ values_a,
                      const float* __restrict__ values_b,
                      const float* __restrict__ v_a,
                      const float* __restrict__ v_b) {
    int sc = blockIdx.x;          // s tile (0..31)
    int nh = blockIdx.y;          // h quarter (0..3)
    int zb = blockIdx.z;          // head*32 + b
    int head = zb >> 5;
    int b    = zb & 31;
    const float* V  = head ? values_b : values_a;
    const float* vv = head ? v_b : v_a;

    extern __shared__ char smem[];
    uint32_t sb = smem_u32(smem);
    int tid = threadIdx.x, lane = tid & 31, wid = tid >> 5;
    int warp_m = wid & 1, warp_n = wid >> 1;

    float acc[4][4][4];
    #pragma unroll
    for (int mf = 0; mf < 4; mf++)
        #pragma unroll
        for (int nf = 0; nf < 4; nf++)
            #pragma unroll
            for (int r = 0; r < 4; r++) acc[mf][nf][r] = 0.0f;

    const float* Vbase = V + ((size_t)b * SS + (size_t)sc * 128) * KD;
    const __nv_bfloat16* Bh_src = &g_Bt_hi[head][0][0] + (size_t)nh * 128 * KD;
    const __nv_bfloat16* Bl_src = &g_Bt_lo[head][0][0] + (size_t)nh * 128 * KD;

    // ldmatrix per-lane base offsets
    uint32_t aRow = (uint32_t)(warp_m * 64 + (lane & 15));
    uint32_t aCol = (uint32_t)((lane >> 4) * 16);
    uint32_t bRow = (uint32_t)(warp_n * 32 + (lane & 7) + ((lane >> 4) & 1) * 8);
    uint32_t bCol = (uint32_t)(((lane >> 3) & 1) * 16);

    for (int kc = 0; kc < 8; kc++) {
        __syncthreads();
        // ---- stage A: 128x64 fp32 -> hi/lo bf16 (stride 72) ----
        #pragma unroll
        for (int i = 0; i < 4; i++) {
            int idx = i * 256 + tid;
            int r = idx >> 3, g = idx & 7;
            const float* p = Vbase + (size_t)r * KD + kc * 64 + g * 8;
            float4 xa = *(const float4*)p;
            float4 xb = *(const float4*)(p + 4);
            float x[8] = {xa.x, xa.y, xa.z, xa.w, xb.x, xb.y, xb.z, xb.w};
            uint32_t hp[4], lp[4];
            #pragma unroll
            for (int j = 0; j < 4; j++) {
                uint32_t h = pack_bf2(x[2 * j], x[2 * j + 1]);
                float h0 = __uint_as_float(h << 16);
                float h1 = __uint_as_float(h & 0xFFFF0000u);
                hp[j] = h;
                lp[j] = pack_bf2(x[2 * j] - h0, x[2 * j + 1] - h1);
            }
            *(uint4*)(smem + SMA_HI + r * 144 + g * 16) = make_uint4(hp[0], hp[1], hp[2], hp[3]);
            *(uint4*)(smem + SMA_LO + r * 144 + g * 16) = make_uint4(lp[0], lp[1], lp[2], lp[3]);
        }
        // ---- stage B: straight uint4 copy of pre-split Wk^T ----
        #pragma unroll
        for (int i = 0; i < 4; i++) {
            int idx = i * 256 + tid;
            int r = idx >> 3, g = idx & 7;
            size_t soff = (size_t)r * KD + kc * 64 + g * 8;
            *(uint4*)(smem + SMB_HI + r * 144 + g * 16) = *(const uint4*)(Bh_src + soff);
            *(uint4*)(smem + SMB_LO + r * 144 + g * 16) = *(const uint4*)(Bl_src + soff);
        }
        __syncthreads();

        #pragma unroll
        for (int ks = 0; ks < 4; ks++) {
            uint32_t ah[4][4], al[4][4], bb[2][4];
            // load A hi + lo frags (4 m16 frags each)
            #pragma unroll
            for (int mf = 0; mf < 4; mf++) {
                uint32_t off = (aRow + mf * 16) * 144 + ks * 32 + aCol;
                ldsm4(ah[mf][0], ah[mf][1], ah[mf][2], ah[mf][3], sb + SMA_HI + off);
                ldsm4(al[mf][0], al[mf][1], al[mf][2], al[mf][3], sb + SMA_LO + off);
            }
            // load B hi frags (2 pairs = 4 n8 frags)
            #pragma unroll
            for (int p = 0; p < 2; p++) {
                uint32_t off = (bRow + p * 16) * 144 + ks * 32 + bCol;
                ldsm4(bb[p][0], bb[p][1], bb[p][2], bb[p][3], sb + SMB_HI + off);
            }
            // Ah*Bh and Al*Bh
            #pragma unroll
            for (int mf = 0; mf < 4; mf++)
                #pragma unroll
                for (int p = 0; p < 2; p++) {
                    mma_bf16(acc[mf][2 * p + 0], ah[mf], &bb[p][0]);
                    mma_bf16(acc[mf][2 * p + 1], ah[mf], &bb[p][2]);
                    mma_bf16(acc[mf][2 * p + 0], al[mf], &bb[p][0]);
                    mma_bf16(acc[mf][2 * p + 1], al[mf], &bb[p][2]);
                }
            // load B lo frags (overwrite bb)
            #pragma unroll
            for (int p = 0; p < 2; p++) {
                uint32_t off = (bRow + p * 16) * 144 + ks * 32 + bCol;
                ldsm4(bb[p][0], bb[p][1], bb[p][2], bb[p][3], sb + SMB_LO + off);
            }
            // Ah*Bl
            #pragma unroll
            for (int mf = 0; mf < 4; mf++)
                #pragma unroll
                for (int p = 0; p < 2; p++) {
                    mma_bf16(acc[mf][2 * p + 0], ah[mf], &bb[p][0]);
                    mma_bf16(acc[mf][2 * p + 1], ah[mf], &bb[p][2]);
                }
        }
    }

    // ---- epilogue: partial score per row = sum_h v[h]*tanh(pq[h]+C) ----
    __syncthreads();
    float* ps  = (float*)(smem + SM_PS);
    float* vs  = (float*)(smem + SM_VS);
    float* red = (float*)(smem + SM_RED);
    if (tid < 128) {
        ps[tid] = g_pq[head][b][nh * 128 + tid];
        vs[tid] = vv[nh * 128 + tid];
    }
    __syncthreads();

    #pragma unroll
    for (int mf = 0; mf < 4; mf++) {
        float slo = 0.0f, shi = 0.0f;
        #pragma unroll
        for (int nf = 0; nf < 4; nf++) {
            int h = warp_n * 32 + nf * 8 + (lane & 3) * 2;
            slo = fmaf(vs[h],     tanh_fast(acc[mf][nf][0] + ps[h]),     slo);
            slo = fmaf(vs[h + 1], tanh_fast(acc[mf][nf][1] + ps[h + 1]), slo);
            shi = fmaf(vs[h],     tanh_fast(acc[mf][nf][2] + ps[h]),     shi);
            shi = fmaf(vs[h + 1], tanh_fast(acc[mf][nf][3] + ps[h + 1]), shi);
        }
        slo += __shfl_xor_sync(0xffffffffu, slo, 1);
        slo += __shfl_xor_sync(0xffffffffu, slo, 2);
        shi += __shfl_xor_sync(0xffffffffu, shi, 1);
        shi += __shfl_xor_sync(0xffffffffu, shi, 2);
        if ((lane & 3) == 0) {
            int row = warp_m * 64 + mf * 16 + (lane >> 2);
            red[row * 4 + warp_n]       = slo;
            red[(row + 8) * 4 + warp_n] = shi;
        }
    }
    __syncthreads();
    if (tid < 128) {
        float s = red[tid * 4 + 0] + red[tid * 4 + 1] +
                  red[tid * 4 + 2] + red[tid * 4 + 3];
        g_scp[nh][head][b][sc * 128 + tid] = s;
    }
}

// ---------------------------------------------------------------------------
// sparsemax (binary search on tau) + context + write alphas.
__global__ void sparsemax_kernel(const float* __restrict__ values_a,
                                 const float* __restrict__ values_b,
                                 float* __restrict__ out) {
    int head = blockIdx.x >> 5;
    int b    = blockIdx.x & 31;
    const float* V = head ? values_b : values_a;

    __shared__ float z[SS];
    __shared__ float wred[16];
    __shared__ float bcast;

    int tid  = threadIdx.x;
    int lane = tid & 31;
    int wid  = tid >> 5;

    float lmax = -3.0e38f;
    for (int i = tid; i < SS; i += 512) {
        float sc = (g_scp[0][head][b][i] + g_scp[1][head][b][i]) +
                   (g_scp[2][head][b][i] + g_scp[3][head][b][i]);
        float zz = (g_maskf[head][b][i] != 0.0f) ? sc : NEGV;
        z[i] = zz;
        lmax = fmaxf(lmax, zz);
    }
    #pragma unroll
    for (int off = 16; off > 0; off >>= 1)
        lmax = fmaxf(lmax, __shfl_xor_sync(0xffffffffu, lmax, off));
    if (lane == 0) wred[wid] = lmax;
    __syncthreads();
    if (tid == 0) {
        float m = wred[0];
        for (int w = 1; w < 16; w++) m = fmaxf(m, wred[w]);
        bcast = m;
    }
    __syncthreads();
    float zmax = bcast;

    float lo = zmax - 1.0f, hi = zmax;
    for (int it = 0; it < 40; it++) {
        float mid = 0.5f * (lo + hi);
        float s = 0.0f;
        for (int i = tid; i < SS; i += 512) s += fmaxf(z[i] - mid, 0.0f);
        #pragma unroll
        for (int off = 16; off > 0; off >>= 1)
            s += __shfl_xor_sync(0xffffffffu, s, off);
        if (lane == 0) wred[wid] = s;
        __syncthreads();
        if (tid == 0) {
            float tot = 0.0f;
            for (int w = 0; w < 16; w++) tot += wred[w];
            bcast = tot;
        }
        __syncthreads();
        float tot = bcast;
        if (tot >= 1.0f) lo = mid; else hi = mid;
        __syncthreads();
    }
    float tau = 0.5f * (lo + hi);

    float* alout = out + OUT_AL + (size_t)head * BB * SS + (size_t)b * SS;
    for (int i = tid; i < SS; i += 512) {
        float a = fmaxf(z[i] - tau, 0.0f);
        alout[i] = a;
        z[i] = a;
    }
    __syncthreads();

    const float* Vb = V + (size_t)b * SS * KD;
    float ctx = 0.0f;
    for (int s = 0; s < SS; s++) {
        float a = z[s];
        if (a > 0.0f) ctx = fmaf(a, Vb[(size_t)s * KD + tid], ctx);
    }
    g_ctx[head][b][tid] = ctx;
}

// ---------------------------------------------------------------------------
__global__ void merge_kernel(const float* __restrict__ query,
                             const float* __restrict__ Wg,
                             const float* __restrict__ bg,
                             const float* __restrict__ Wu_a,
                             const float* __restrict__ bu_a,
                             const float* __restrict__ Wu_b,
                             const float* __restrict__ bu_b,
                             float* __restrict__ out) {
    int b = blockIdx.x;
    int t = threadIdx.x;
    int lane = t & 31, wid = t >> 5;
    __shared__ float qv[HD], ca[KD], cb[KD];
    __shared__ float red0[16], red1[16];
    __shared__ float w01[2];

    qv[t] = query[b * HD + t];
    ca[t] = g_ctx[0][b][t];
    cb[t] = g_ctx[1][b][t];
    __syncthreads();

    float p0 = 0.0f, p1 = 0.0f;
    {
        float x = qv[t];
        p0 = fmaf(x, Wg[t * 2 + 0], p0);  p1 = fmaf(x, Wg[t * 2 + 1], p1);
        x = ca[t];
        p0 = fmaf(x, Wg[(512 + t) * 2 + 0], p0);  p1 = fmaf(x, Wg[(512 + t) * 2 + 1], p1);
        x = cb[t];
        p0 = fmaf(x, Wg[(1024 + t) * 2 + 0], p0); p1 = fmaf(x, Wg[(1024 + t) * 2 + 1], p1);
    }
    #pragma unroll
    for (int off = 16; off > 0; off >>= 1) {
        p0 += __shfl_xor_sync(0xffffffffu, p0, off);
        p1 += __shfl_xor_sync(0xffffffffu, p1, off);
    }
    if (lane == 0) { red0[wid] = p0; red1[wid] = p1; }
    __syncthreads();
    if (t == 0) {
        float g0 = bg[0], g1 = bg[1];
        for (int w = 0; w < 16; w++) { g0 += red0[w]; g1 += red1[w]; }
        float m = fmaxf(g0, g1);
        float e0 = expf(g0 - m), e1 = expf(g1 - m);
        float inv = 1.0f / (e0 + e1);
        w01[0] = e0 * inv;
        w01[1] = e1 * inv;
    }
    __syncthreads();
    float w0 = w01[0], w1 = w01[1];

    float sa = bu_a[t], sb2 = bu_b[t];
    for (int i = 0; i < 512; i++) {
        float q = qv[i];
        sa  = fmaf(q, Wu_a[i * HD + t], sa);
        sb2 = fmaf(q, Wu_b[i * HD + t], sb2);
    }
    for (int i = 0; i < 512; i++) {
        sa  = fmaf(ca[i], Wu_a[(512 + i) * HD + t], sa);
        sb2 = fmaf(cb[i], Wu_b[(512 + i) * HD + t], sb2);
    }
    out[OUT_ATT + b * HD + t] = w0 * tanhf(sa) + w1 * tanhf(sb2);
}

// ---------------------------------------------------------------------------
extern "C" void kernel_launch(void* const* d_in, const int* in_sizes, int n_in,
                              void* d_out, int out_size) {
    const float* query    = (const float*)d_in[0];
    const float* values_a = (const float*)d_in[1];
    const float* values_b = (const float*)d_in[2];
    const void*  mask_a   = d_in[3];
    const void*  mask_b   = d_in[4];
    const float* Wk_a = (const float*)d_in[5];
    const float* Wq_a = (const float*)d_in[6];
    const float* v_a  = (const float*)d_in[7];
    const float* Wk_b = (const float*)d_in[8];
    const float* Wq_b = (const float*)d_in[9];
    const float* v_b  = (const float*)d_in[10];
    const float* Wg   = (const float*)d_in[11];
    const float* bg   = (const float*)d_in[12];
    const float* Wu_a = (const float*)d_in[13];
    const float* bu_a = (const float*)d_in[14];
    const float* Wu_b = (const float*)d_in[15];
    const float* bu_b = (const float*)d_in[16];
    float* out = (float*)d_out;

    cudaFuncSetAttribute(score_mma_kernel,
                         cudaFuncAttributeMaxDynamicSharedMemorySize, SM_TOTAL);

    detect_kernel<<<1, 256>>>((const unsigned char*)mask_a);
    mask_convert_kernel<<<512, 512>>>(mask_a, mask_b);
    dim3 gp(16, 16, 2);
    prep_wk_kernel<<<gp, dim3(32, 8)>>>(Wk_a, Wk_b);
    pq_kernel<<<64, 512>>>(query, Wq_a, Wq_b);
    dim3 g1(32, 4, 64);
    score_mma_kernel<<<g1, 256, SM_TOTAL>>>(values_a, values_b, v_a, v_b);
    sparsemax_kernel<<<64, 512>>>(values_a, values_b, out);
    merge_kernel<<<32, 512>>>(query, Wg, bg, Wu_a, bu_a, Wu_b, bu_b, out);
}

// round 5
// speedup vs baseline: 2.9610x; 1.1794x over previous
#include <cuda_runtime.h>
#include <cuda_bf16.h>
#include <math.h>
#include <stdint.h>

// Problem constants
#define BB 32
#define SS 4096
#define KD 512
#define HD 512
#define NEGV (-1e9f)
#define MARGIN 0.125f
#define MAXCAND 512

// Output layout: [att_vector (32*512) | al_a (32*4096) | al_b (32*4096)]
#define OUT_ATT 0
#define OUT_AL  (BB*HD)

// Scratch (device globals; no allocations allowed)
__device__ float g_pq[2][BB][HD];
__device__ float g_scp[4][2][BB][SS];     // per-nh partial approx scores
__device__ float g_scores[2][BB][SS];     // masked scores (approx, then refined)
__device__ float g_ctx[2][BB][KD];
__device__ float g_maskf[2][BB][SS];
__device__ int   g_mask_mode;
__device__ __nv_bfloat16 g_Bt[2][HD][KD]; // transposed bf16 Wk: g_Bt[h][n][k]
__device__ int   g_cand[2][BB][MAXCAND];
__device__ int   g_ccnt[2][BB];

// ---------------------------------------------------------------------------
__device__ __forceinline__ float tanh_fast(float x) {
    float cx = fminf(fmaxf(x, -15.0f), 15.0f);
    float e = __expf(2.0f * cx);
    return __fdividef(e - 1.0f, e + 1.0f);
}

__device__ __forceinline__ uint32_t smem_u32(const void* p) {
    uint32_t a;
    asm("{ .reg .u64 t; cvta.to.shared.u64 t, %1; cvt.u32.u64 %0, t; }"
        : "=r"(a) : "l"(p));
    return a;
}

// pack two floats -> bf16x2 (x0 low half, x1 high half)
__device__ __forceinline__ uint32_t pack_bf2(float x0, float x1) {
    uint32_t d;
    asm("cvt.rn.satfinite.bf16x2.f32 %0, %1, %2;" : "=r"(d) : "f"(x1), "f"(x0));
    return d;
}

__device__ __forceinline__ void ldsm4(uint32_t& r0, uint32_t& r1,
                                      uint32_t& r2, uint32_t& r3, uint32_t a) {
    asm volatile("ldmatrix.sync.aligned.m8n8.x4.shared.b16 {%0,%1,%2,%3}, [%4];"
                 : "=r"(r0), "=r"(r1), "=r"(r2), "=r"(r3) : "r"(a));
}

__device__ __forceinline__ void mma_bf16(float* c, const uint32_t* a,
                                         const uint32_t* b) {
    asm volatile(
        "mma.sync.aligned.m16n8k16.row.col.f32.bf16.bf16.f32 "
        "{%0,%1,%2,%3}, {%4,%5,%6,%7}, {%8,%9}, {%0,%1,%2,%3};"
        : "+f"(c[0]), "+f"(c[1]), "+f"(c[2]), "+f"(c[3])
        : "r"(a[0]), "r"(a[1]), "r"(a[2]), "r"(a[3]), "r"(b[0]), "r"(b[1]));
}

// ---------------------------------------------------------------------------
// Mask dtype detection (int32 on this dataset, keep generic)
__global__ void detect_kernel(const unsigned char* __restrict__ m) {
    __shared__ int c[4];
    if (threadIdx.x < 4) c[threadIdx.x] = 0;
    __syncthreads();
    int local[4] = {0, 0, 0, 0};
    for (int i = threadIdx.x; i < 32768; i += blockDim.x)
        if (m[i]) local[i & 3]++;
    #pragma unroll
    for (int j = 0; j < 4; j++) if (local[j]) atomicAdd(&c[j], local[j]);
    __syncthreads();
    if (threadIdx.x == 0) {
        int mode;
        if (c[1] > 0)      mode = 0;
        else if (c[0] > 0) mode = 1;
        else               mode = 2;
        g_mask_mode = mode;
    }
}

__global__ void mask_convert_kernel(const void* __restrict__ ma,
                                    const void* __restrict__ mb) {
    int idx = blockIdx.x * blockDim.x + threadIdx.x;
    int head = idx >> 17;
    int i    = idx & 131071;
    const void* p = head ? mb : ma;
    int mode = g_mask_mode;
    float keep;
    if (mode == 0)      keep = ((const unsigned char*)p)[i] ? 1.0f : 0.0f;
    else if (mode == 1) keep = ((const int*)p)[i] ? 1.0f : 0.0f;
    else                keep = (((const float*)p)[i] != 0.0f) ? 1.0f : 0.0f;
    ((float*)g_maskf)[idx] = keep;
}

// ---------------------------------------------------------------------------
// Transpose Wk into g_Bt[head][n][k] (single bf16). Tiled via smem.
__global__ void prep_wk_kernel(const float* __restrict__ Wk_a,
                               const float* __restrict__ Wk_b) {
    __shared__ float tile[32][33];
    int head = blockIdx.z;
    const float* Wk = head ? Wk_b : Wk_a;
    int kt = blockIdx.x * 32, nt = blockIdx.y * 32;
    int tx = threadIdx.x, ty = threadIdx.y;
    #pragma unroll
    for (int i = 0; i < 4; i++)
        tile[ty + i * 8][tx] = Wk[(kt + ty + i * 8) * HD + nt + tx];
    __syncthreads();
    #pragma unroll
    for (int i = 0; i < 4; i++) {
        int n = nt + ty + i * 8;
        int k = kt + tx;
        g_Bt[head][n][k] = __float2bfloat16(tile[tx][ty + i * 8]);
    }
}

// ---------------------------------------------------------------------------
// pq[head][b][h] = sum_k query[b][k] * Wq[k][h]
__global__ void pq_kernel(const float* __restrict__ query,
                          const float* __restrict__ Wq_a,
                          const float* __restrict__ Wq_b) {
    int head = blockIdx.x >> 5;
    int b    = blockIdx.x & 31;
    const float* Wq = head ? Wq_b : Wq_a;
    __shared__ float q[HD];
    int t = threadIdx.x;
    q[t] = query[b * HD + t];
    __syncthreads();
    float s0 = 0.f, s1 = 0.f, s2 = 0.f, s3 = 0.f;
    #pragma unroll 4
    for (int k = 0; k < HD; k += 4) {
        s0 = fmaf(q[k + 0], Wq[(k + 0) * HD + t], s0);
        s1 = fmaf(q[k + 1], Wq[(k + 1) * HD + t], s1);
        s2 = fmaf(q[k + 2], Wq[(k + 2) * HD + t], s2);
        s3 = fmaf(q[k + 3], Wq[(k + 3) * HD + t], s3);
    }
    g_pq[head][b][t] = (s0 + s1) + (s2 + s3);
}

// ---------------------------------------------------------------------------
// Hot kernel: SINGLE-product bf16 mma.sync GEMM (approx scores).
// Grid (sc=32, nh=4, zb=64), block 256 (8 warps: 2m x 4n). Tile 128x128, k64.
// Double-buffered smem staging; rows stride 72 bf16 (144B).
#define BUFSZ 36864           // A (18432) + B (18432) per buffer
#define SM_PS  73728
#define SM_VS  74240
#define SM_RED 74752
#define SM_TOTAL 76800

__device__ __forceinline__ void stage_tile(char* smem, int buf, int kc,
                                           const float* Vbase,
                                           const __nv_bfloat16* Bsrc, int tid) {
    char* A = smem + buf * BUFSZ;
    char* Bp = A + 18432;
    #pragma unroll
    for (int i = 0; i < 4; i++) {
        int idx = i * 256 + tid;
        int r = idx >> 3, g = idx & 7;
        const float* p = Vbase + (size_t)r * KD + kc * 64 + g * 8;
        float4 xa = *(const float4*)p;
        float4 xb = *(const float4*)(p + 4);
        uint32_t h0 = pack_bf2(xa.x, xa.y), h1 = pack_bf2(xa.z, xa.w);
        uint32_t h2 = pack_bf2(xb.x, xb.y), h3 = pack_bf2(xb.z, xb.w);
        *(uint4*)(A + r * 144 + g * 16) = make_uint4(h0, h1, h2, h3);
        *(uint4*)(Bp + r * 144 + g * 16) =
            *(const uint4*)(Bsrc + (size_t)r * KD + kc * 64 + g * 8);
    }
}

__global__ __launch_bounds__(256, 2)
void score_mma_kernel(const float* __restrict__ values_a,
                      const float* __restrict__ values_b,
                      const float* __restrict__ v_a,
                      const float* __restrict__ v_b) {
    int sc = blockIdx.x;
    int nh = blockIdx.y;
    int zb = blockIdx.z;
    int head = zb >> 5;
    int b    = zb & 31;
    const float* V  = head ? values_b : values_a;
    const float* vv = head ? v_b : v_a;

    extern __shared__ char smem[];
    uint32_t sb = smem_u32(smem);
    int tid = threadIdx.x, lane = tid & 31, wid = tid >> 5;
    int warp_m = wid & 1, warp_n = wid >> 1;

    float acc[4][4][4];
    #pragma unroll
    for (int mf = 0; mf < 4; mf++)
        #pragma unroll
        for (int nf = 0; nf < 4; nf++)
            #pragma unroll
            for (int r = 0; r < 4; r++) acc[mf][nf][r] = 0.0f;

    const float* Vbase = V + ((size_t)b * SS + (size_t)sc * 128) * KD;
    const __nv_bfloat16* Bsrc = &g_Bt[head][nh * 128][0];

    uint32_t aRow = (uint32_t)(warp_m * 64 + (lane & 15));
    uint32_t aCol = (uint32_t)((lane >> 4) * 16);
    uint32_t bRow = (uint32_t)(warp_n * 32 + (lane & 7) + ((lane >> 4) & 1) * 8);
    uint32_t bCol = (uint32_t)(((lane >> 3) & 1) * 16);

    stage_tile(smem, 0, 0, Vbase, Bsrc, tid);

    for (int kc = 0; kc < 8; kc++) {
        __syncthreads();
        int cur = kc & 1;
        uint32_t Ab = sb + cur * BUFSZ;
        uint32_t Bb = Ab + 18432;
        #pragma unroll
        for (int ks = 0; ks < 4; ks++) {
            uint32_t af[4][4], bf[2][4];
            #pragma unroll
            for (int mf = 0; mf < 4; mf++) {
                uint32_t off = (aRow + mf * 16) * 144 + ks * 32 + aCol;
                ldsm4(af[mf][0], af[mf][1], af[mf][2], af[mf][3], Ab + off);
            }
            #pragma unroll
            for (int p = 0; p < 2; p++) {
                uint32_t off = (bRow + p * 16) * 144 + ks * 32 + bCol;
                ldsm4(bf[p][0], bf[p][1], bf[p][2], bf[p][3], Bb + off);
            }
            #pragma unroll
            for (int mf = 0; mf < 4; mf++)
                #pragma unroll
                for (int p = 0; p < 2; p++) {
                    mma_bf16(acc[mf][2 * p + 0], af[mf], &bf[p][0]);
                    mma_bf16(acc[mf][2 * p + 1], af[mf], &bf[p][2]);
                }
        }
        if (kc < 7) stage_tile(smem, cur ^ 1, kc + 1, Vbase, Bsrc, tid);
    }

    // epilogue: partial score per row = sum_h v[h]*tanh(pq[h]+C)
    __syncthreads();
    float* ps  = (float*)(smem + SM_PS);
    float* vs  = (float*)(smem + SM_VS);
    float* red = (float*)(smem + SM_RED);
    if (tid < 128) {
        ps[tid] = g_pq[head][b][nh * 128 + tid];
        vs[tid] = vv[nh * 128 + tid];
    }
    __syncthreads();

    #pragma unroll
    for (int mf = 0; mf < 4; mf++) {
        float slo = 0.0f, shi = 0.0f;
        #pragma unroll
        for (int nf = 0; nf < 4; nf++) {
            int h = warp_n * 32 + nf * 8 + (lane & 3) * 2;
            slo = fmaf(vs[h],     tanh_fast(acc[mf][nf][0] + ps[h]),     slo);
            slo = fmaf(vs[h + 1], tanh_fast(acc[mf][nf][1] + ps[h + 1]), slo);
            shi = fmaf(vs[h],     tanh_fast(acc[mf][nf][2] + ps[h]),     shi);
            shi = fmaf(vs[h + 1], tanh_fast(acc[mf][nf][3] + ps[h + 1]), shi);
        }
        slo += __shfl_xor_sync(0xffffffffu, slo, 1);
        slo += __shfl_xor_sync(0xffffffffu, slo, 2);
        shi += __shfl_xor_sync(0xffffffffu, shi, 1);
        shi += __shfl_xor_sync(0xffffffffu, shi, 2);
        if ((lane & 3) == 0) {
            int row = warp_m * 64 + mf * 16 + (lane >> 2);
            red[row * 4 + warp_n]       = slo;
            red[(row + 8) * 4 + warp_n] = shi;
        }
    }
    __syncthreads();
    if (tid < 128) {
        float s = red[tid * 4 + 0] + red[tid * 4 + 1] +
                  red[tid * 4 + 2] + red[tid * 4 + 3];
        g_scp[nh][head][b][sc * 128 + tid] = s;
    }
}

// ---------------------------------------------------------------------------
// Pass 1: assemble masked approx scores, bisect tau_approx, emit candidates.
__global__ void spmax_pass1_kernel() {
    int head = blockIdx.x >> 5;
    int b    = blockIdx.x & 31;

    __shared__ float z[SS];
    __shared__ float wred[16];
    __shared__ float bcast;
    __shared__ int scnt;

    int tid  = threadIdx.x;
    int lane = tid & 31;
    int wid  = tid >> 5;
    if (tid == 0) scnt = 0;

    float lmax = -3.0e38f;
    for (int i = tid; i < SS; i += 512) {
        float sc = (g_scp[0][head][b][i] + g_scp[1][head][b][i]) +
                   (g_scp[2][head][b][i] + g_scp[3][head][b][i]);
        float zz = (g_maskf[head][b][i] != 0.0f) ? sc : NEGV;
        z[i] = zz;
        g_scores[head][b][i] = zz;
        lmax = fmaxf(lmax, zz);
    }
    #pragma unroll
    for (int off = 16; off > 0; off >>= 1)
        lmax = fmaxf(lmax, __shfl_xor_sync(0xffffffffu, lmax, off));
    if (lane == 0) wred[wid] = lmax;
    __syncthreads();
    if (tid == 0) {
        float m = wred[0];
        for (int w = 1; w < 16; w++) m = fmaxf(m, wred[w]);
        bcast = m;
    }
    __syncthreads();
    float zmax = bcast;

    float lo = zmax - 1.0f, hi = zmax;
    for (int it = 0; it < 30; it++) {
        float mid = 0.5f * (lo + hi);
        float s = 0.0f;
        for (int i = tid; i < SS; i += 512) s += fmaxf(z[i] - mid, 0.0f);
        #pragma unroll
        for (int off = 16; off > 0; off >>= 1)
            s += __shfl_xor_sync(0xffffffffu, s, off);
        if (lane == 0) wred[wid] = s;
        __syncthreads();
        if (tid == 0) {
            float tot = 0.0f;
            for (int w = 0; w < 16; w++) tot += wred[w];
            bcast = tot;
        }
        __syncthreads();
        float tot = bcast;
        if (tot >= 1.0f) lo = mid; else hi = mid;
        __syncthreads();
    }
    float tau = 0.5f * (lo + hi);

    float thr = tau - MARGIN;
    for (int i = tid; i < SS; i += 512) {
        if (z[i] > thr) {
            int p = atomicAdd(&scnt, 1);
            if (p < MAXCAND) g_cand[head][b][p] = i;
        }
    }
    __syncthreads();
    if (tid == 0) g_ccnt[head][b] = scnt < MAXCAND ? scnt : MAXCAND;
}

// ---------------------------------------------------------------------------
// Refine: exact fp32 scores for candidate rows. One block per (head,b).
__global__ __launch_bounds__(256)
void refine_kernel(const float* __restrict__ values_a,
                   const float* __restrict__ values_b,
                   const float* __restrict__ Wk_a,
                   const float* __restrict__ Wk_b,
                   const float* __restrict__ v_a,
                   const float* __restrict__ v_b) {
    int head = blockIdx.x >> 5;
    int b    = blockIdx.x & 31;
    const float* V  = head ? values_b : values_a;
    const float* Wk = head ? Wk_b : Wk_a;
    const float* vv = head ? v_b : v_a;

    __shared__ float vrow[8][512];     // 16 KB
    __shared__ float red[8][8];

    int t = threadIdx.x, lane = t & 31, wid = t >> 5;
    float pq0 = g_pq[head][b][t], pq1 = g_pq[head][b][t + 256];
    float vv0 = vv[t], vv1 = vv[t + 256];

    int cnt = g_ccnt[head][b];
    for (int base = 0; base < cnt; base += 8) {
        #pragma unroll
        for (int g = 0; g < 8; g++) {
            int ci = base + g;
            if (ci < cnt) {
                int row = g_cand[head][b][ci];
                const float* src = V + ((size_t)b * SS + row) * KD;
                for (int j = t; j < 512; j += 256) vrow[g][j] = src[j];
            } else {
                for (int j = t; j < 512; j += 256) vrow[g][j] = 0.0f;
            }
        }
        __syncthreads();

        float a0[8], a1[8];
        #pragma unroll
        for (int g = 0; g < 8; g++) { a0[g] = 0.0f; a1[g] = 0.0f; }
        for (int k = 0; k < 512; k++) {
            float w0 = Wk[k * HD + t];
            float w1 = Wk[k * HD + t + 256];
            #pragma unroll
            for (int g = 0; g < 8; g++) {
                float x = vrow[g][k];
                a0[g] = fmaf(x, w0, a0[g]);
                a1[g] = fmaf(x, w1, a1[g]);
            }
        }
        #pragma unroll
        for (int g = 0; g < 8; g++) {
            float s = vv0 * tanh_fast(pq0 + a0[g]) + vv1 * tanh_fast(pq1 + a1[g]);
            #pragma unroll
            for (int off = 16; off > 0; off >>= 1)
                s += __shfl_xor_sync(0xffffffffu, s, off);
            if (lane == 0) red[g][wid] = s;
        }
        __syncthreads();
        if (t < 8) {
            int ci = base + t;
            if (ci < cnt) {
                float s = 0.0f;
                #pragma unroll
                for (int w = 0; w < 8; w++) s += red[t][w];
                g_scores[head][b][g_cand[head][b][ci]] = s;
            }
        }
        __syncthreads();
    }
}

// ---------------------------------------------------------------------------
// Pass 2: final sparsemax on refined scores + context + alphas.
__global__ void sparsemax_kernel(const float* __restrict__ values_a,
                                 const float* __restrict__ values_b,
                                 float* __restrict__ out) {
    int head = blockIdx.x >> 5;
    int b    = blockIdx.x & 31;
    const float* V = head ? values_b : values_a;

    __shared__ float z[SS];
    __shared__ float wred[16];
    __shared__ float bcast;

    int tid  = threadIdx.x;
    int lane = tid & 31;
    int wid  = tid >> 5;

    float lmax = -3.0e38f;
    for (int i = tid; i < SS; i += 512) {
        float zz = g_scores[head][b][i];
        z[i] = zz;
        lmax = fmaxf(lmax, zz);
    }
    #pragma unroll
    for (int off = 16; off > 0; off >>= 1)
        lmax = fmaxf(lmax, __shfl_xor_sync(0xffffffffu, lmax, off));
    if (lane == 0) wred[wid] = lmax;
    __syncthreads();
    if (tid == 0) {
        float m = wred[0];
        for (int w = 1; w < 16; w++) m = fmaxf(m, wred[w]);
        bcast = m;
    }
    __syncthreads();
    float zmax = bcast;

    float lo = zmax - 1.0f, hi = zmax;
    for (int it = 0; it < 40; it++) {
        float mid = 0.5f * (lo + hi);
        float s = 0.0f;
        for (int i = tid; i < SS; i += 512) s += fmaxf(z[i] - mid, 0.0f);
        #pragma unroll
        for (int off = 16; off > 0; off >>= 1)
            s += __shfl_xor_sync(0xffffffffu, s, off);
        if (lane == 0) wred[wid] = s;
        __syncthreads();
        if (tid == 0) {
            float tot = 0.0f;
            for (int w = 0; w < 16; w++) tot += wred[w];
            bcast = tot;
        }
        __syncthreads();
        float tot = bcast;
        if (tot >= 1.0f) lo = mid; else hi = mid;
        __syncthreads();
    }
    float tau = 0.5f * (lo + hi);

    float* alout = out + OUT_AL + (size_t)head * BB * SS + (size_t)b * SS;
    for (int i = tid; i < SS; i += 512) {
        float a = fmaxf(z[i] - tau, 0.0f);
        alout[i] = a;
        z[i] = a;
    }
    __syncthreads();

    const float* Vb = V + (size_t)b * SS * KD;
    float ctx = 0.0f;
    for (int s = 0; s < SS; s++) {
        float a = z[s];
        if (a > 0.0f) ctx = fmaf(a, Vb[(size_t)s * KD + tid], ctx);
    }
    g_ctx[head][b][tid] = ctx;
}

// ---------------------------------------------------------------------------
__global__ void merge_kernel(const float* __restrict__ query,
                             const float* __restrict__ Wg,
                             const float* __restrict__ bg,
                             const float* __restrict__ Wu_a,
                             const float* __restrict__ bu_a,
                             const float* __restrict__ Wu_b,
                             const float* __restrict__ bu_b,
                             float* __restrict__ out) {
    int b = blockIdx.x;
    int t = threadIdx.x;
    int lane = t & 31, wid = t >> 5;
    __shared__ float qv[HD], ca[KD], cb[KD];
    __shared__ float red0[16], red1[16];
    __shared__ float w01[2];

    qv[t] = query[b * HD + t];
    ca[t] = g_ctx[0][b][t];
    cb[t] = g_ctx[1][b][t];
    __syncthreads();

    float p0 = 0.0f, p1 = 0.0f;
    {
        float x = qv[t];
        p0 = fmaf(x, Wg[t * 2 + 0], p0);  p1 = fmaf(x, Wg[t * 2 + 1], p1);
        x = ca[t];
        p0 = fmaf(x, Wg[(512 + t) * 2 + 0], p0);  p1 = fmaf(x, Wg[(512 + t) * 2 + 1], p1);
        x = cb[t];
        p0 = fmaf(x, Wg[(1024 + t) * 2 + 0], p0); p1 = fmaf(x, Wg[(1024 + t) * 2 + 1], p1);
    }
    #pragma unroll
    for (int off = 16; off > 0; off >>= 1) {
        p0 += __shfl_xor_sync(0xffffffffu, p0, off);
        p1 += __shfl_xor_sync(0xffffffffu, p1, off);
    }
    if (lane == 0) { red0[wid] = p0; red1[wid] = p1; }
    __syncthreads();
    if (t == 0) {
        float g0 = bg[0], g1 = bg[1];
        for (int w = 0; w < 16; w++) { g0 += red0[w]; g1 += red1[w]; }
        float m = fmaxf(g0, g1);
        float e0 = expf(g0 - m), e1 = expf(g1 - m);
        float inv = 1.0f / (e0 + e1);
        w01[0] = e0 * inv;
        w01[1] = e1 * inv;
    }
    __syncthreads();
    float w0 = w01[0], w1 = w01[1];

    float sa = bu_a[t], sb2 = bu_b[t];
    for (int i = 0; i < 512; i++) {
        float q = qv[i];
        sa  = fmaf(q, Wu_a[i * HD + t], sa);
        sb2 = fmaf(q, Wu_b[i * HD + t], sb2);
    }
    for (int i = 0; i < 512; i++) {
        sa  = fmaf(ca[i], Wu_a[(512 + i) * HD + t], sa);
        sb2 = fmaf(cb[i], Wu_b[(512 + i) * HD + t], sb2);
    }
    out[OUT_ATT + b * HD + t] = w0 * tanhf(sa) + w1 * tanhf(sb2);
}

// ---------------------------------------------------------------------------
extern "C" void kernel_launch(void* const* d_in, const int* in_sizes, int n_in,
                              void* d_out, int out_size) {
    const float* query    = (const float*)d_in[0];
    const float* values_a = (const float*)d_in[1];
    const float* values_b = (const float*)d_in[2];
    const void*  mask_a   = d_in[3];
    const void*  mask_b   = d_in[4];
    const float* Wk_a = (const float*)d_in[5];
    const float* Wq_a = (const float*)d_in[6];
    const float* v_a  = (const float*)d_in[7];
    const float* Wk_b = (const float*)d_in[8];
    const float* Wq_b = (const float*)d_in[9];
    const float* v_b  = (const float*)d_in[10];
    const float* Wg   = (const float*)d_in[11];
    const float* bg   = (const float*)d_in[12];
    const float* Wu_a = (const float*)d_in[13];
    const float* bu_a = (const float*)d_in[14];
    const float* Wu_b = (const float*)d_in[15];
    const float* bu_b = (const float*)d_in[16];
    float* out = (float*)d_out;

    cudaFuncSetAttribute(score_mma_kernel,
                         cudaFuncAttributeMaxDynamicSharedMemorySize, SM_TOTAL);

    detect_kernel<<<1, 256>>>((const unsigned char*)mask_a);
    mask_convert_kernel<<<512, 512>>>(mask_a, mask_b);
    dim3 gp(16, 16, 2);
    prep_wk_kernel<<<gp, dim3(32, 8)>>>(Wk_a, Wk_b);
    pq_kernel<<<64, 512>>>(query, Wq_a, Wq_b);
    dim3 g1(32, 4, 64);
    score_mma_kernel<<<g1, 256, SM_TOTAL>>>(values_a, values_b, v_a, v_b);
    spmax_pass1_kernel<<<64, 512>>>();
    refine_kernel<<<64, 256>>>(values_a, values_b, Wk_a, Wk_b, v_a, v_b);
    sparsemax_kernel<<<64, 512>>>(values_a, values_b, out);
    merge_kernel<<<32, 512>>>(query, Wg, bg, Wu_a, bu_a, Wu_b, bu_b, out);
}